// round 2
// baseline (speedup 1.0000x reference)
#include <cuda_runtime.h>
#include <cstdint>

#define B_  64
#define T_  512
#define H_  128
#define G4  512            // 4*H
#define M_  (B_*T_)        // 32768

// ---------------- static device scratch (no runtime allocation allowed) --------
__device__ float g_x0[M_*128];                    // embedded input [M][128]
__device__ float g_ya[M_*256];                    // layer output ping [M][2H]
__device__ float g_yb[M_*256];                    // layer output pong
__device__ float g_xg[2u*M_*G4];                  // [dir][M][4H] input projections

#define FMA2(acc, a, b) asm("fma.rn.f32x2 %0, %1, %2, %0;" : "+l"(acc) : "l"(a), "l"(b))

// ---------------- embedding gather ----------------
__global__ void embed_kernel(const int* __restrict__ idx,
                             const float* __restrict__ emb,
                             float* __restrict__ x0) {
    int i = blockIdx.x * 256 + threadIdx.x;   // over M_*128
    if (i < M_ * 128) {
        x0[i] = emb[(size_t)idx[i >> 7] * 128 + (i & 127)];
    }
}

// ---------------- xg GEMM: out[dir][m][n] = sum_k A[m][k]*W[dir][n][k] + bi + bh
// 64x64 tile, 256 threads, 4x4 micro-tile, f32x2 packed FMA.
__global__ __launch_bounds__(256) void xg_gemm_kernel(
    const float* __restrict__ A,     // [M_][K]
    const float* __restrict__ W,     // [2][512][K]
    const float* __restrict__ bi,    // [2][512]
    const float* __restrict__ bh,    // [2][512]
    float* __restrict__ out,         // [2][M_][512]
    int K)
{
    __shared__ __align__(16) float2 Asd[32][66];   // [k][m] = (a,a), swizzled cols
    __shared__ __align__(16) float  Wsh[32][68];   // [k][n]

    int dir = blockIdx.z;
    const float* Wd = W + (size_t)dir * G4 * K;
    int m0 = blockIdx.x * 64, n0 = blockIdx.y * 64;
    int tid = threadIdx.x;
    int tx = tid & 15, ty = tid >> 4;

    unsigned long long acc[4][2] = {};
    float ra[8], rw[8];

#pragma unroll
    for (int r = 0; r < 8; r++) {
        int idxv = r * 256 + tid;
        int k = idxv & 31, mm = idxv >> 5;
        ra[r] = A[(size_t)(m0 + mm) * K + k];
        rw[r] = Wd[(size_t)(n0 + mm) * K + k];
    }

    int KT = K >> 5;
    for (int kt = 0; kt < KT; kt++) {
#pragma unroll
        for (int r = 0; r < 8; r++) {
            int idxv = r * 256 + tid;
            int k = idxv & 31, mm = idxv >> 5;
            int cs = ((((mm >> 2) ^ (k & 3)) << 2) | (mm & 3));  // swizzle groups of 4
            Asd[k][cs] = make_float2(ra[r], ra[r]);
            Wsh[k][mm] = rw[r];
        }
        __syncthreads();

        if (kt + 1 < KT) {
            int kb = (kt + 1) << 5;
#pragma unroll
            for (int r = 0; r < 8; r++) {
                int idxv = r * 256 + tid;
                int k = idxv & 31, mm = idxv >> 5;
                ra[r] = A[(size_t)(m0 + mm) * K + kb + k];
                rw[r] = Wd[(size_t)(n0 + mm) * K + kb + k];
            }
        }

#pragma unroll
        for (int k = 0; k < 32; k++) {
            int cb = (ty ^ (k & 3)) << 2;
            const ulonglong2* ap = reinterpret_cast<const ulonglong2*>(&Asd[k][cb]);
            ulonglong2 a01 = ap[0];                 // (a_m0,a_m0),(a_m1,a_m1)
            ulonglong2 a23 = ap[1];
            ulonglong2 bb  = *reinterpret_cast<const ulonglong2*>(&Wsh[k][tx << 2]);
            FMA2(acc[0][0], a01.x, bb.x); FMA2(acc[0][1], a01.x, bb.y);
            FMA2(acc[1][0], a01.y, bb.x); FMA2(acc[1][1], a01.y, bb.y);
            FMA2(acc[2][0], a23.x, bb.x); FMA2(acc[2][1], a23.x, bb.y);
            FMA2(acc[3][0], a23.y, bb.x); FMA2(acc[3][1], a23.y, bb.y);
        }
        __syncthreads();
    }

    int nb = n0 + (tx << 2);
    float bs0 = bi[dir * G4 + nb + 0] + bh[dir * G4 + nb + 0];
    float bs1 = bi[dir * G4 + nb + 1] + bh[dir * G4 + nb + 1];
    float bs2 = bi[dir * G4 + nb + 2] + bh[dir * G4 + nb + 2];
    float bs3 = bi[dir * G4 + nb + 3] + bh[dir * G4 + nb + 3];

    float* od = out + (size_t)dir * M_ * G4;
#pragma unroll
    for (int i = 0; i < 4; i++) {
        unsigned int u0, u1, u2, u3;
        asm("mov.b64 {%0, %1}, %2;" : "=r"(u0), "=r"(u1) : "l"(acc[i][0]));
        asm("mov.b64 {%0, %1}, %2;" : "=r"(u2), "=r"(u3) : "l"(acc[i][1]));
        float4 v = make_float4(__uint_as_float(u0) + bs0,
                               __uint_as_float(u1) + bs1,
                               __uint_as_float(u2) + bs2,
                               __uint_as_float(u3) + bs3);
        int m = m0 + (ty << 2) + i;
        *reinterpret_cast<float4*>(&od[(size_t)m * G4 + nb]) = v;
    }
}

// ---------------- recurrent scan: 128 blocks = 64 batch x 2 dir ----------------
// Thread g owns gate row g. 96 w_hh k-values in regs, 32 in smem (k-major).
// dyn smem: swt 64KB | sg 2KB | sh 512B
#define REC_SMEM (16*512*8 + 512*4 + 128*4)

__global__ __launch_bounds__(512, 1) void lstm_rec_kernel(
    const float* __restrict__ xg,    // [2][B][T][4H]
    const float* __restrict__ whh,   // [2][4H][H]
    const float* __restrict__ h0,    // [2][B][H]  (layer slice of hx)
    const float* __restrict__ c0,    // [2][B][H]
    float* __restrict__ y)           // [B][T][2H]
{
    extern __shared__ __align__(16) char sm_[];
    unsigned long long* swt = reinterpret_cast<unsigned long long*>(sm_); // [16][512]
    float* sg = reinterpret_cast<float*>(sm_ + 16*512*8);                 // [512]
    float* sh = sg + 512;                                                 // [128]

    int b = blockIdx.x, dir = blockIdx.y, g = threadIdx.x;

    // load weight row g: k 0..95 -> regs (as f32x2 pairs), k 96..127 -> smem k-major
    const ulonglong2* w2 = reinterpret_cast<const ulonglong2*>(
        whh + ((size_t)dir * G4 + g) * H_);
    unsigned long long wreg[48];
#pragma unroll
    for (int j = 0; j < 24; j++) { ulonglong2 u = w2[j]; wreg[2*j] = u.x; wreg[2*j+1] = u.y; }
#pragma unroll
    for (int j = 0; j < 8; j++) {
        ulonglong2 u = w2[24 + j];
        swt[(size_t)(2*j) * 512 + g]   = u.x;
        swt[(size_t)(2*j+1) * 512 + g] = u.y;
    }

    float c = 0.f;
    if (g < H_) {
        c     = c0[((size_t)dir * B_ + b) * H_ + g];
        sh[g] = h0[((size_t)dir * B_ + b) * H_ + g];
    }

    const float* xp = xg + ((size_t)dir * B_ + b) * T_ * G4;
    float* yp = y + (size_t)b * T_ * 256 + dir * H_;
    int t  = dir ? (T_ - 1) : 0;
    int dt = dir ? -1 : 1;
    __syncthreads();

    float xgv = xp[(size_t)t * G4 + g];

    for (int s = 0; s < T_; s++) {
        float xnext = 0.f;
        if (s + 1 < T_) xnext = xp[(size_t)(t + dt) * G4 + g];   // prefetch

        const ulonglong2* sh4 = reinterpret_cast<const ulonglong2*>(sh);
        unsigned long long a0 = 0ull, a1 = 0ull;
#pragma unroll
        for (int j = 0; j < 24; j++) {
            ulonglong2 hq = sh4[j];
            FMA2(a0, wreg[2*j],   hq.x);
            FMA2(a1, wreg[2*j+1], hq.y);
        }
        const unsigned long long* swp = swt + g;
#pragma unroll
        for (int j = 0; j < 8; j++) {
            ulonglong2 hq = sh4[24 + j];
            FMA2(a0, swp[(size_t)(2*j) * 512],   hq.x);
            FMA2(a1, swp[(size_t)(2*j+1) * 512], hq.y);
        }
        unsigned lo0, hi0, lo1, hi1;
        asm("mov.b64 {%0,%1}, %2;" : "=r"(lo0), "=r"(hi0) : "l"(a0));
        asm("mov.b64 {%0,%1}, %2;" : "=r"(lo1), "=r"(hi1) : "l"(a1));
        sg[g] = xgv + __uint_as_float(lo0) + __uint_as_float(hi0)
                    + __uint_as_float(lo1) + __uint_as_float(hi1);
        __syncthreads();

        if (g < H_) {
            float gi = sg[g], gf = sg[g + 128], gc = sg[g + 256], go = sg[g + 384];
            float si = __fdividef(1.f, 1.f + __expf(-gi));
            float sf = __fdividef(1.f, 1.f + __expf(-gf));
            float so = __fdividef(1.f, 1.f + __expf(-go));
            float tc = __fdividef(2.f, 1.f + __expf(-2.f * gc)) - 1.f;
            c = sf * c + si * tc;
            float th = __fdividef(2.f, 1.f + __expf(-2.f * c)) - 1.f;
            float h = so * th;
            sh[g] = h;
            yp[(size_t)t * 256 + g] = h;
        }
        xgv = xnext;
        t += dt;
        __syncthreads();
    }
}

// ---------------- linear head on last timestep ----------------
__global__ void head_kernel(const float* __restrict__ y,
                            const float* __restrict__ lw,
                            const float* __restrict__ lb,
                            float* __restrict__ out) {
    int b = blockIdx.x, tid = threadIdx.x;   // 256 threads
    float v = y[((size_t)b * T_ + (T_ - 1)) * 256 + tid] * lw[tid];
#pragma unroll
    for (int o = 16; o; o >>= 1) v += __shfl_xor_sync(0xffffffffu, v, o);
    __shared__ float red[8];
    if ((tid & 31) == 0) red[tid >> 5] = v;
    __syncthreads();
    if (tid == 0) {
        float s = lb[0];
#pragma unroll
        for (int i = 0; i < 8; i++) s += red[i];
        out[b] = s;
    }
}

// ---------------- launch ----------------
extern "C" void kernel_launch(void* const* d_in, const int* in_sizes, int n_in,
                              void* d_out, int out_size) {
    const int*   X   = (const int*)d_in[0];
    const float* emb = (const float*)d_in[1];
    const float* hx  = (const float*)d_in[2];
    const float* cx  = (const float*)d_in[3];
    const float* lw  = (const float*)d_in[4];
    const float* lb  = (const float*)d_in[5];
    const float* wih[3] = {(const float*)d_in[6],  (const float*)d_in[10], (const float*)d_in[14]};
    const float* whh[3] = {(const float*)d_in[7],  (const float*)d_in[11], (const float*)d_in[15]};
    const float* bih[3] = {(const float*)d_in[8],  (const float*)d_in[12], (const float*)d_in[16]};
    const float* bhh[3] = {(const float*)d_in[9],  (const float*)d_in[13], (const float*)d_in[17]};

    cudaFuncSetAttribute(lstm_rec_kernel,
                         cudaFuncAttributeMaxDynamicSharedMemorySize, REC_SMEM);

    float *x0, *ya, *yb, *xgd;
    cudaGetSymbolAddress((void**)&x0,  g_x0);
    cudaGetSymbolAddress((void**)&ya,  g_ya);
    cudaGetSymbolAddress((void**)&yb,  g_yb);
    cudaGetSymbolAddress((void**)&xgd, g_xg);

    embed_kernel<<<(M_ * 128 + 255) / 256, 256>>>(X, emb, x0);

    const float* in = x0;
    int K = 128;
    float* youts[3] = {ya, yb, ya};
    for (int l = 0; l < 3; l++) {
        dim3 gg(M_ / 64, G4 / 64, 2);
        xg_gemm_kernel<<<gg, 256>>>(in, wih[l], bih[l], bhh[l], xgd, K);
        lstm_rec_kernel<<<dim3(B_, 2), 512, REC_SMEM>>>(
            xgd, whh[l], hx + (size_t)l * 2 * B_ * H_, cx + (size_t)l * 2 * B_ * H_, youts[l]);
        in = youts[l];
        K = 256;
    }
    head_kernel<<<B_, 256>>>(youts[2], lw, lb, (float*)d_out);
}

// round 4
// speedup vs baseline: 1.4099x; 1.4099x over previous
#include <cuda_runtime.h>
#include <cuda_bf16.h>
#include <cstdint>

#define B_  64
#define T_  512
#define H_  128
#define G4  512            // 4*H
#define M_  (B_*T_)        // 32768

// ---------------- static device scratch (no runtime allocation allowed) --------
__device__ float g_x0[M_*128];                            // embedded input [M][128]
__device__ float g_ya[M_*256];                            // layer output ping
__device__ float g_yb[M_*256];                            // layer output pong
__device__ float g_xg[2u*M_*G4];                          // [dir][M][4H] projections
__device__ __align__(16) __nv_bfloat16 g_a3[(size_t)M_*768];   // split acts [M][3K]
__device__ __align__(16) __nv_bfloat16 g_w3[3][2*512*768];     // split weights

#define FMA2(acc, a, b) asm("fma.rn.f32x2 %0, %1, %2, %0;" : "+l"(acc) : "l"(a), "l"(b))

// ---------------- embedding gather ----------------
__global__ void embed_kernel(const int* __restrict__ idx,
                             const float* __restrict__ emb,
                             float* __restrict__ x0) {
    int i = blockIdx.x * 256 + threadIdx.x;
    if (i < M_ * 128) {
        x0[i] = emb[(size_t)idx[i >> 7] * 128 + (i & 127)];
    }
}

// ---------------- fp32 -> bf16 hi/lo split, K-concat layout ----------------
__global__ void split_kernel(const float* __restrict__ in,
                             __nv_bfloat16* __restrict__ out,
                             int K, int dup_off, int lo_off, int total) {
    int i = blockIdx.x * 256 + threadIdx.x;
    if (i >= total) return;
    int m = i / K, k = i - m * K;
    float a = in[i];
    __nv_bfloat16 hi = __float2bfloat16_rn(a);
    float lo = a - __bfloat162float(hi);
    __nv_bfloat16 lob = __float2bfloat16_rn(lo);
    size_t base = (size_t)m * (3 * K);
    out[base + k] = hi;
    out[base + dup_off + k] = hi;
    out[base + lo_off + k] = lob;
}

// ---------------- mma.sync bf16 GEMM ------------------------------------------
// out[dir][m][n] = A3[m][:] . W3[dir][n][:] + bias.  CTA 128m x 128n, 8 warps,
// warp tile 64x32.  Smem staged in fragment-major order (no ldmatrix needed).
#define MMA_BF16(c0,c1,c2,c3, a0,a1,a2,a3, b0,b1)                                \
    asm volatile("mma.sync.aligned.m16n8k16.row.col.f32.bf16.bf16.f32 "          \
        "{%0,%1,%2,%3}, {%4,%5,%6,%7}, {%8,%9}, {%0,%1,%2,%3};"                  \
        : "+f"(c0), "+f"(c1), "+f"(c2), "+f"(c3)                                 \
        : "r"(a0), "r"(a1), "r"(a2), "r"(a3), "r"(b0), "r"(b1))

__global__ __launch_bounds__(256, 1)
void mma_gemm_kernel(const __nv_bfloat16* __restrict__ A3,   // [M][K3]
                     const __nv_bfloat16* __restrict__ W3,   // [2][512][K3]
                     const float* __restrict__ bi,           // [2][512]
                     const float* __restrict__ bh,           // [2][512]
                     float* __restrict__ out,                // [2][M][512]
                     int K3)
{
    // fragment-major staging: A [k16][mt16][lane][4 regs], B [k16][nt8][lane][2 regs]
    __shared__ __align__(16) uint32_t As[4096];   // 16KB
    __shared__ __align__(16) uint32_t Bs[4096];   // 16KB

    int tid = threadIdx.x, wid = tid >> 5, lane = tid & 31;
    int wm = wid >> 2, wn = wid & 3;
    int m0 = blockIdx.x * 128;
    int n0 = blockIdx.y * 128;
    int dir = blockIdx.z;
    const __nv_bfloat16* Wd = W3 + (size_t)(dir * 512 + n0) * K3;
    const __nv_bfloat16* Am = A3 + (size_t)m0 * K3;

    float acc[4][4][4];
#pragma unroll
    for (int i = 0; i < 4; i++)
#pragma unroll
        for (int j = 0; j < 4; j++)
#pragma unroll
            for (int q = 0; q < 4; q++) acc[i][j][q] = 0.f;

    const int NC = K3 >> 6;
    uint4 ra[4], rb[4];

    // preload chunk 0
#pragma unroll
    for (int j = 0; j < 4; j++) {
        int idx = j * 256 + tid; int r = idx >> 3, c = idx & 7;
        ra[j] = *(const uint4*)(Am + (size_t)r * K3 + c * 8);
        rb[j] = *(const uint4*)(Wd + (size_t)r * K3 + c * 8);
    }

    for (int ch = 0; ch < NC; ch++) {
        // ---- stage to smem in fragment order ----
#pragma unroll
        for (int j = 0; j < 4; j++) {
            int idx = j * 256 + tid; int r = idx >> 3, c = idx & 7;
            int k16 = c >> 1;
            int rrA = ((r >> 3) & 1) + 2 * (c & 1);
            int mt = r >> 4;
            int rrB = (c & 1);
            int nt = r >> 3;
            uint32_t w[4] = {ra[j].x, ra[j].y, ra[j].z, ra[j].w};
            uint32_t v[4] = {rb[j].x, rb[j].y, rb[j].z, rb[j].w};
#pragma unroll
            for (int p = 0; p < 4; p++) {
                int ls = (((r & 7) << 2) + p) ^ k16;
                As[(((k16 * 8 + mt) * 32 + ls) << 2) + rrA] = w[p];
                Bs[(((k16 * 16 + nt) * 32 + ls) << 1) + rrB] = v[p];
            }
        }
        __syncthreads();

        // ---- prefetch next chunk ----
        if (ch + 1 < NC) {
            int kb = (ch + 1) * 64;
#pragma unroll
            for (int j = 0; j < 4; j++) {
                int idx = j * 256 + tid; int r = idx >> 3, c = idx & 7;
                ra[j] = *(const uint4*)(Am + (size_t)r * K3 + kb + c * 8);
                rb[j] = *(const uint4*)(Wd + (size_t)r * K3 + kb + c * 8);
            }
        }

        // ---- mma over 4 k16 steps ----
#pragma unroll
        for (int k16 = 0; k16 < 4; k16++) {
            int lx = lane ^ k16;
            uint4 af[4]; uint2 bf[4];
#pragma unroll
            for (int i = 0; i < 4; i++)
                af[i] = *(const uint4*)&As[(((k16 * 8 + wm * 4 + i) * 32 + lx) << 2)];
#pragma unroll
            for (int j = 0; j < 4; j++)
                bf[j] = *(const uint2*)&Bs[(((k16 * 16 + wn * 4 + j) * 32 + lx) << 1)];
#pragma unroll
            for (int i = 0; i < 4; i++)
#pragma unroll
                for (int j = 0; j < 4; j++)
                    MMA_BF16(acc[i][j][0], acc[i][j][1], acc[i][j][2], acc[i][j][3],
                             af[i].x, af[i].y, af[i].z, af[i].w, bf[j].x, bf[j].y);
        }
        __syncthreads();
    }

    // ---- epilogue: bias + store fp32 ----
    int g = lane >> 2, t = lane & 3;
#pragma unroll
    for (int j = 0; j < 4; j++) {
        int n = n0 + wn * 32 + j * 8 + t * 2;
        float b0 = bi[dir * G4 + n]     + bh[dir * G4 + n];
        float b1 = bi[dir * G4 + n + 1] + bh[dir * G4 + n + 1];
#pragma unroll
        for (int i = 0; i < 4; i++) {
            int m = m0 + wm * 64 + i * 16 + g;
            float* o0 = out + (size_t)dir * M_ * G4 + (size_t)m * G4 + n;
            *(float2*)o0 = make_float2(acc[i][j][0] + b0, acc[i][j][1] + b1);
            float* o1 = o0 + 8 * G4;
            *(float2*)o1 = make_float2(acc[i][j][2] + b0, acc[i][j][3] + b1);
        }
    }
}

// ---------------- recurrent scan: 128 blocks = 64 batch x 2 dir ----------------
#define REC_SMEM (16*512*8 + 512*4 + 128*4)

__global__ __launch_bounds__(512, 1) void lstm_rec_kernel(
    const float* __restrict__ xg,    // [2][B][T][4H]
    const float* __restrict__ whh,   // [2][4H][H]
    const float* __restrict__ h0,    // [2][B][H]
    const float* __restrict__ c0,    // [2][B][H]
    float* __restrict__ y)           // [B][T][2H]
{
    extern __shared__ __align__(16) char sm_[];
    unsigned long long* swt = reinterpret_cast<unsigned long long*>(sm_); // [16][512]
    float* sg = reinterpret_cast<float*>(sm_ + 16*512*8);                 // [512]
    float* sh = sg + 512;                                                 // [128]

    int b = blockIdx.x, dir = blockIdx.y, g = threadIdx.x;

    const ulonglong2* w2 = reinterpret_cast<const ulonglong2*>(
        whh + ((size_t)dir * G4 + g) * H_);
    unsigned long long wreg[48];
#pragma unroll
    for (int j = 0; j < 24; j++) { ulonglong2 u = w2[j]; wreg[2*j] = u.x; wreg[2*j+1] = u.y; }
#pragma unroll
    for (int j = 0; j < 8; j++) {
        ulonglong2 u = w2[24 + j];
        swt[(size_t)(2*j) * 512 + g]   = u.x;
        swt[(size_t)(2*j+1) * 512 + g] = u.y;
    }

    float c = 0.f;
    if (g < H_) {
        c     = c0[((size_t)dir * B_ + b) * H_ + g];
        sh[g] = h0[((size_t)dir * B_ + b) * H_ + g];
    }

    const float* xp = xg + ((size_t)dir * B_ + b) * T_ * G4;
    float* yp = y + (size_t)b * T_ * 256 + dir * H_;
    int t  = dir ? (T_ - 1) : 0;
    int dt = dir ? -1 : 1;
    bool is_g = ((g >> 7) == 2);      // cell-candidate gate -> tanh
    __syncthreads();

    float xgv = xp[(size_t)t * G4 + g];

    for (int s = 0; s < T_; s++) {
        float xnext = 0.f;
        if (s + 1 < T_) xnext = xp[(size_t)(t + dt) * G4 + g];   // prefetch

        const ulonglong2* sh4 = reinterpret_cast<const ulonglong2*>(sh);
        unsigned long long a0 = 0ull, a1 = 0ull;
#pragma unroll
        for (int j = 0; j < 24; j++) {
            ulonglong2 hq = sh4[j];
            FMA2(a0, wreg[2*j],   hq.x);
            FMA2(a1, wreg[2*j+1], hq.y);
        }
        const unsigned long long* swp = swt + g;
#pragma unroll
        for (int j = 0; j < 8; j++) {
            ulonglong2 hq = sh4[24 + j];
            FMA2(a0, swp[(size_t)(2*j) * 512],   hq.x);
            FMA2(a1, swp[(size_t)(2*j+1) * 512], hq.y);
        }
        unsigned lo0, hi0, lo1, hi1;
        asm("mov.b64 {%0,%1}, %2;" : "=r"(lo0), "=r"(hi0) : "l"(a0));
        asm("mov.b64 {%0,%1}, %2;" : "=r"(lo1), "=r"(hi1) : "l"(a1));
        float gv = xgv + __uint_as_float(lo0) + __uint_as_float(hi0)
                       + __uint_as_float(lo1) + __uint_as_float(hi1);
        // activation in-register on all 512 threads
        float act;
        if (is_g) act = __fdividef(2.f, 1.f + __expf(-2.f * gv)) - 1.f;   // tanh
        else      act = __fdividef(1.f, 1.f + __expf(-gv));               // sigmoid
        sg[g] = act;
        __syncthreads();

        if (g < H_) {
            float si = sg[g], sf = sg[g + 128], tg = sg[g + 256], so = sg[g + 384];
            c = sf * c + si * tg;
            float th = __fdividef(2.f, 1.f + __expf(-2.f * c)) - 1.f;
            float h = so * th;
            sh[g] = h;
            yp[(size_t)t * 256 + g] = h;
        }
        xgv = xnext;
        t += dt;
        __syncthreads();
    }
}

// ---------------- linear head on last timestep ----------------
__global__ void head_kernel(const float* __restrict__ y,
                            const float* __restrict__ lw,
                            const float* __restrict__ lb,
                            float* __restrict__ out) {
    int b = blockIdx.x, tid = threadIdx.x;   // 256 threads
    float v = y[((size_t)b * T_ + (T_ - 1)) * 256 + tid] * lw[tid];
#pragma unroll
    for (int o = 16; o; o >>= 1) v += __shfl_xor_sync(0xffffffffu, v, o);
    __shared__ float red[8];
    if ((tid & 31) == 0) red[tid >> 5] = v;
    __syncthreads();
    if (tid == 0) {
        float s = lb[0];
#pragma unroll
        for (int i = 0; i < 8; i++) s += red[i];
        out[b] = s;
    }
}

// ---------------- launch ----------------
extern "C" void kernel_launch(void* const* d_in, const int* in_sizes, int n_in,
                              void* d_out, int out_size) {
    const int*   X   = (const int*)d_in[0];
    const float* emb = (const float*)d_in[1];
    const float* hx  = (const float*)d_in[2];
    const float* cx  = (const float*)d_in[3];
    const float* lw  = (const float*)d_in[4];
    const float* lb  = (const float*)d_in[5];
    const float* wih[3] = {(const float*)d_in[6],  (const float*)d_in[10], (const float*)d_in[14]};
    const float* whh[3] = {(const float*)d_in[7],  (const float*)d_in[11], (const float*)d_in[15]};
    const float* bih[3] = {(const float*)d_in[8],  (const float*)d_in[12], (const float*)d_in[16]};
    const float* bhh[3] = {(const float*)d_in[9],  (const float*)d_in[13], (const float*)d_in[17]};

    cudaFuncSetAttribute(lstm_rec_kernel,
                         cudaFuncAttributeMaxDynamicSharedMemorySize, REC_SMEM);

    float *x0, *ya, *yb, *xgd;
    __nv_bfloat16 *a3, *w3;
    cudaGetSymbolAddress((void**)&x0,  g_x0);
    cudaGetSymbolAddress((void**)&ya,  g_ya);
    cudaGetSymbolAddress((void**)&yb,  g_yb);
    cudaGetSymbolAddress((void**)&xgd, g_xg);
    cudaGetSymbolAddress((void**)&a3,  g_a3);
    cudaGetSymbolAddress((void**)&w3,  g_w3);

    const int Ks[3] = {128, 256, 256};

    // weight splits: hi at [k],[K+k]; lo at [2K+k]
    for (int l = 0; l < 3; l++) {
        int K = Ks[l], total = 2 * 512 * K;
        split_kernel<<<(total + 255) / 256, 256>>>(
            wih[l], w3 + (size_t)l * (2 * 512 * 768), K, K, 2 * K, total);
    }

    embed_kernel<<<(M_ * 128 + 255) / 256, 256>>>(X, emb, x0);

    const float* in = x0;
    float* youts[3] = {ya, yb, ya};
    for (int l = 0; l < 3; l++) {
        int K = Ks[l], K3 = 3 * K;
        int total = M_ * K;
        // activation split: hi at [k],[2K+k]; lo at [K+k]
        split_kernel<<<(total + 255) / 256, 256>>>(in, a3, K, 2 * K, K, total);
        mma_gemm_kernel<<<dim3(M_ / 128, 4, 2), 256>>>(
            a3, w3 + (size_t)l * (2 * 512 * 768), bih[l], bhh[l], xgd, K3);
        lstm_rec_kernel<<<dim3(B_, 2), 512, REC_SMEM>>>(
            xgd, whh[l], hx + (size_t)l * 2 * B_ * H_, cx + (size_t)l * 2 * B_ * H_, youts[l]);
        in = youts[l];
    }
    head_kernel<<<B_, 256>>>(youts[2], lw, lb, (float*)d_out);
}